// round 3
// baseline (speedup 1.0000x reference)
#include <cuda_runtime.h>
#include <cuda_bf16.h>
#include <cstdint>

// Problem constants (fixed shapes in the reference):
//   N=50000 nodes, E=800000 edges, IN_DIM=128, H=8, D=16 -> C = H*D = 128
#define NN 50000
#define EE 800000
#define CC 128
#define KK 128

// ---------------- device scratch (__device__ globals: the sanctioned way) ---
__device__ float d_z[NN * CC];          // per-node projected features [N,128]
__device__ int   d_cnt[NN];             // in-degree histogram, then scatter cursor
__device__ int   d_off[NN + 1];         // CSR row offsets by dst
__device__ int   d_csr_src[EE];         // src node ids grouped by dst

// ---------------- CSR construction ------------------------------------------
__global__ void k_zero_cnt() {
    int i = blockIdx.x * blockDim.x + threadIdx.x;
    if (i < NN) d_cnt[i] = 0;
}

__global__ void k_hist(const int* __restrict__ dst) {
    int e = blockIdx.x * blockDim.x + threadIdx.x;
    if (e < EE) atomicAdd(&d_cnt[dst[e]], 1);
}

// Single-block exclusive scan over d_cnt -> d_off; resets d_cnt to be the
// scatter cursor (initialized to the row start).
__global__ void k_scan() {
    __shared__ int s[1024];
    const int t = threadIdx.x;
    const int chunk = (NN + 1023) / 1024;           // 49
    const int lo = t * chunk;
    const int hi = min(lo + chunk, NN);

    int total = 0;
    for (int i = lo; i < hi; ++i) total += d_cnt[i];

    s[t] = total;
    __syncthreads();
    // Hillis-Steele inclusive scan
    for (int off = 1; off < 1024; off <<= 1) {
        int v = (t >= off) ? s[t - off] : 0;
        __syncthreads();
        s[t] += v;
        __syncthreads();
    }
    int run = s[t] - total;                          // exclusive prefix
    for (int i = lo; i < hi; ++i) {
        int c = d_cnt[i];
        d_off[i] = run;
        d_cnt[i] = run;                              // becomes cursor
        run += c;
    }
    if (t == 0) d_off[NN] = EE;
}

__global__ void k_scatter(const int* __restrict__ src, const int* __restrict__ dst) {
    int e = blockIdx.x * blockDim.x + threadIdx.x;
    if (e < EE) {
        int pos = atomicAdd(&d_cnt[dst[e]], 1);
        d_csr_src[pos] = src[e];
    }
}

// ---------------- GEMM: z[n, h*16+d] = sum_i h[n,i] * Wfc[h,i,d] ------------
// Block: 256 threads, BM=32 nodes, K tiled by 64.
// warp w handles nodes base+4w..base+4w+3; lane handles 4 consecutive outputs.
#define BM 32
#define BK 64

__global__ void __launch_bounds__(256) k_gemm(const float* __restrict__ hin,
                                              const float* __restrict__ Wfc) {
    __shared__ float sW[BK][CC + 4];     // +4 pad keeps rows 16B-aligned
    __shared__ float sH[BM][BK + 4];

    const int tid  = threadIdx.x;
    const int lane = tid & 31;
    const int warp = tid >> 5;           // 0..7
    const int base = blockIdx.x * BM;

    float acc[4][4];
#pragma unroll
    for (int a = 0; a < 4; ++a)
#pragma unroll
        for (int b = 0; b < 4; ++b) acc[a][b] = 0.f;

    for (int k0 = 0; k0 < KK; k0 += BK) {
        // Load W chunk: sW[k][hh*16+d] = Wfc[hh*2048 + (k0+k)*16 + d]
        for (int idx = tid; idx < BK * CC; idx += 256) {
            int hh = idx >> 10;          // 64 k-rows * 16 d = 1024 per head
            int r  = idx & 1023;
            int k  = r >> 4;
            int dd = r & 15;
            sW[k][hh * 16 + dd] = Wfc[hh * 2048 + (k0 + k) * 16 + dd];
        }
        // Load H chunk
        for (int idx = tid; idx < BM * BK; idx += 256) {
            int nrow = idx >> 6;         // /64
            int k    = idx & 63;
            int gn   = base + nrow;
            sH[nrow][k] = (gn < NN) ? hin[gn * KK + k0 + k] : 0.f;
        }
        __syncthreads();

#pragma unroll 8
        for (int k = 0; k < BK; ++k) {
            float4 w = *(const float4*)&sW[k][lane * 4];
#pragma unroll
            for (int j = 0; j < 4; ++j) {
                float hv = sH[warp * 4 + j][k];
                acc[j][0] += hv * w.x;
                acc[j][1] += hv * w.y;
                acc[j][2] += hv * w.z;
                acc[j][3] += hv * w.w;
            }
        }
        __syncthreads();
    }

#pragma unroll
    for (int j = 0; j < 4; ++j) {
        int gn = base + warp * 4 + j;
        if (gn < NN) {
            float4 v = make_float4(acc[j][0], acc[j][1], acc[j][2], acc[j][3]);
            *(float4*)&d_z[gn * CC + lane * 4] = v;
        }
    }
}

// ---------------- per-dst-node softmax aggregation + epilogue ---------------
// One warp per node; lane owns channels [4*lane, 4*lane+4).
// No max-shift needed: |e| <= ~35 so exp(e) is fp32-safe (exp(35)~1.6e15,
// exp(-35)~6e-16, both representable); sum(exp*zs)/sum(exp) equals the
// reference's max-shifted softmax exactly in real arithmetic.
__device__ __forceinline__ float elu1(float v) {
    return v > 0.f ? v : expm1f(v);
}

__device__ __forceinline__ void edge_accum(const float4 za, const float4 zd,
                                           float& dx, float& dy, float& dz, float& dw,
                                           float& nx, float& ny, float& nz, float& nw) {
    float ex;
    ex = __expf(za.x * zd.x); dx += ex; nx += ex * za.x;
    ex = __expf(za.y * zd.y); dy += ex; ny += ex * za.y;
    ex = __expf(za.z * zd.z); dz += ex; nz += ex * za.z;
    ex = __expf(za.w * zd.w); dw += ex; nw += ex * za.w;
}

__global__ void __launch_bounds__(256) k_agg(const float* __restrict__ hin,
                                             const float* __restrict__ snorm,
                                             float* __restrict__ out) {
    const int gwarp = (blockIdx.x * blockDim.x + threadIdx.x) >> 5;
    const int lane  = threadIdx.x & 31;
    if (gwarp >= NN) return;
    const int node = gwarp;

    const float4 zd = *(const float4*)&d_z[node * CC + lane * 4];
    float dx = 0.f, dy = 0.f, dz = 0.f, dw = 0.f;
    float nx = 0.f, ny = 0.f, nz = 0.f, nw = 0.f;

    const int p0 = d_off[node];
    const int p1 = d_off[node + 1];

    int p = p0;
    // unroll by 4: front-batch the index loads + z gathers for MLP
    for (; p + 3 < p1; p += 4) {
        int s0 = __ldg(&d_csr_src[p]);
        int s1 = __ldg(&d_csr_src[p + 1]);
        int s2 = __ldg(&d_csr_src[p + 2]);
        int s3 = __ldg(&d_csr_src[p + 3]);
        float4 z0 = *(const float4*)&d_z[s0 * CC + lane * 4];
        float4 z1 = *(const float4*)&d_z[s1 * CC + lane * 4];
        float4 z2 = *(const float4*)&d_z[s2 * CC + lane * 4];
        float4 z3 = *(const float4*)&d_z[s3 * CC + lane * 4];
        edge_accum(z0, zd, dx, dy, dz, dw, nx, ny, nz, nw);
        edge_accum(z1, zd, dx, dy, dz, dw, nx, ny, nz, nw);
        edge_accum(z2, zd, dx, dy, dz, dw, nx, ny, nz, nw);
        edge_accum(z3, zd, dx, dy, dz, dw, nx, ny, nz, nw);
    }
    for (; p < p1; ++p) {
        int s0 = __ldg(&d_csr_src[p]);
        float4 z0 = *(const float4*)&d_z[s0 * CC + lane * 4];
        edge_accum(z0, zd, dx, dy, dz, dw, nx, ny, nz, nw);
    }

    const float sn = __ldg(&snorm[node]);
    float4 hv = *(const float4*)&hin[node * CC + lane * 4];

    float4 o;
    o.x = hv.x + elu1((dx > 0.f ? nx / dx : 0.f) * sn);
    o.y = hv.y + elu1((dy > 0.f ? ny / dy : 0.f) * sn);
    o.z = hv.z + elu1((dz > 0.f ? nz / dz : 0.f) * sn);
    o.w = hv.w + elu1((dw > 0.f ? nw / dw : 0.f) * sn);

    *(float4*)&out[node * CC + lane * 4] = o;
}

// ---------------- launch ----------------------------------------------------
extern "C" void kernel_launch(void* const* d_in, const int* in_sizes, int n_in,
                              void* d_out, int out_size) {
    const float* hin   = (const float*)d_in[0];   // [N,128]
    const float* snorm = (const float*)d_in[1];   // [N,1]
    const float* Wfc   = (const float*)d_in[2];   // [8,128,16]
    const int*   src   = (const int*)d_in[3];     // [E]
    const int*   dst   = (const int*)d_in[4];     // [E]
    float* out = (float*)d_out;                   // [N,128]

    k_zero_cnt<<<(NN + 255) / 256, 256>>>();
    k_hist<<<(EE + 255) / 256, 256>>>(dst);
    k_scan<<<1, 1024>>>();
    k_scatter<<<(EE + 255) / 256, 256>>>(src, dst);
    k_gemm<<<(NN + BM - 1) / BM, 256>>>(hin, Wfc);
    k_agg<<<(NN * 32 + 255) / 256, 256>>>(hin, snorm, out);
}

// round 4
// speedup vs baseline: 1.5240x; 1.5240x over previous
#include <cuda_runtime.h>
#include <cuda_bf16.h>
#include <cstdint>

// Problem constants (fixed shapes in the reference):
//   N=50000 nodes, E=800000 edges, IN_DIM=128, H=8, D=16 -> C = H*D = 128
#define NN 50000
#define EE 800000
#define CC 128
#define KK 128

typedef unsigned long long ull;

// ---------------- device scratch --------------------------------------------
__device__ float d_z[NN * CC];          // per-node projected features [N,128]
__device__ int   d_cnt[NN];             // in-degree histogram, then scatter cursor
__device__ int   d_off[NN + 1];         // CSR row offsets by dst
__device__ int   d_csr_src[EE];         // src node ids grouped by dst

#define SB   512
#define NBLK ((NN + SB - 1) / SB)       // 98
__device__ int d_btot[NBLK];
__device__ int d_boff[NBLK];

// ---------------- CSR construction ------------------------------------------
__global__ void k_zero_cnt() {
    int i = blockIdx.x * blockDim.x + threadIdx.x;
    if (i < NN) d_cnt[i] = 0;
}

__global__ void k_hist(const int* __restrict__ dst) {
    int e = blockIdx.x * blockDim.x + threadIdx.x;
    if (e < EE) atomicAdd(&d_cnt[dst[e]], 1);
}

// Hierarchical scan: per-block scan -> block-total scan -> offset add.
__global__ void __launch_bounds__(SB) k_scan1() {
    __shared__ int s[SB];
    const int b = blockIdx.x, t = threadIdx.x, i = b * SB + t;
    int v = (i < NN) ? d_cnt[i] : 0;
    s[t] = v;
    __syncthreads();
    for (int o = 1; o < SB; o <<= 1) {
        int x = (t >= o) ? s[t - o] : 0;
        __syncthreads();
        s[t] += x;
        __syncthreads();
    }
    if (i < NN) d_off[i] = s[t] - v;          // exclusive within block
    if (t == SB - 1) d_btot[b] = s[t];
}

__global__ void __launch_bounds__(128) k_scan2() {
    __shared__ int s[128];
    const int t = threadIdx.x;
    int v = (t < NBLK) ? d_btot[t] : 0;
    s[t] = v;
    __syncthreads();
    for (int o = 1; o < 128; o <<= 1) {
        int x = (t >= o) ? s[t - o] : 0;
        __syncthreads();
        s[t] += x;
        __syncthreads();
    }
    if (t < NBLK) d_boff[t] = s[t] - v;       // exclusive over blocks
}

__global__ void __launch_bounds__(SB) k_scan3() {
    const int b = blockIdx.x, t = threadIdx.x, i = b * SB + t;
    if (i < NN) {
        int o = d_off[i] + d_boff[b];
        d_off[i] = o;
        d_cnt[i] = o;                          // becomes scatter cursor
    }
    if (b == 0 && t == 0) d_off[NN] = EE;
}

__global__ void k_scatter(const int* __restrict__ src, const int* __restrict__ dst) {
    int e = blockIdx.x * blockDim.x + threadIdx.x;
    if (e < EE) {
        int pos = atomicAdd(&d_cnt[dst[e]], 1);
        d_csr_src[pos] = src[e];
    }
}

// ---------------- GEMM via packed fma.rn.f32x2 ------------------------------
// z[n, h*16+d] = sum_k h[n,k] * Wcat[k, h*16+d]  (single 50000x128x128 GEMM;
// Wcat[k][h*16+d] = Wfc[h*2048 + k*16 + d]).
// Block: 256 threads, BM=64 nodes, full K=128 resident.
// Warp w owns nodes n0=w*8..w*8+7; lane owns output cols lane*4..lane*4+3,
// held as 2 packed f32x2 accumulators.
#define GBM 64

__device__ __forceinline__ ull fma2(ull a, ull b, ull c) {
    ull d;
    asm("fma.rn.f32x2 %0, %1, %2, %3;" : "=l"(d) : "l"(a), "l"(b), "l"(c));
    return d;
}
__device__ __forceinline__ ull pack2(float x) {
    ull d;
    asm("mov.b64 %0, {%1, %1};" : "=l"(d) : "f"(x));
    return d;
}

__global__ void __launch_bounds__(256) k_gemm(const float* __restrict__ hin,
                                              const float* __restrict__ Wfc) {
    extern __shared__ float smem[];
    float* sW = smem;                  // [128][128]  sW[k*128 + c]
    float* sH = smem + KK * CC;        // [64][128]   sH[node*128 + k]

    const int tid  = threadIdx.x;
    const int lane = tid & 31;
    const int warp = tid >> 5;
    const int base = blockIdx.x * GBM;
    const int n0   = warp * 8;

    // Load W (transposed to [k][c]): dst float4 index g -> k=g>>5, h=(g>>2)&7, dq=g&3
    {
        const float4* W4 = (const float4*)Wfc;
        float4* sW4 = (float4*)sW;
        for (int g = tid; g < KK * CC / 4; g += 256) {
            int k  = g >> 5;
            int hh = (g >> 2) & 7;
            int dq = g & 3;
            sW4[g] = W4[hh * 512 + k * 4 + dq];
        }
    }
    // Load H tile [64][128]
    {
        const float4* H4 = (const float4*)hin;
        float4* sH4 = (float4*)sH;
        for (int g = tid; g < GBM * KK / 4; g += 256) {
            int row = g >> 5;
            int kq  = g & 31;
            int gn  = base + row;
            sH4[g] = (gn < NN) ? H4[gn * 32 + kq]
                               : make_float4(0.f, 0.f, 0.f, 0.f);
        }
    }
    __syncthreads();

    ull acc[8][2];
#pragma unroll
    for (int j = 0; j < 8; ++j) { acc[j][0] = 0ull; acc[j][1] = 0ull; }

    for (int k = 0; k < KK; k += 4) {
        // w2[kk][0] = cols (lane*4, lane*4+1); w2[kk][1] = cols (+2,+3)
        ull w2[4][2];
#pragma unroll
        for (int kk = 0; kk < 4; ++kk) {
            ulonglong2 wv = *(const ulonglong2*)&sW[(k + kk) * CC + lane * 4];
            w2[kk][0] = wv.x;
            w2[kk][1] = wv.y;
        }
#pragma unroll
        for (int j = 0; j < 8; ++j) {
            const float4 hj = *(const float4*)&sH[(n0 + j) * KK + k];
            ull h0 = pack2(hj.x), h1 = pack2(hj.y), h2 = pack2(hj.z), h3 = pack2(hj.w);
            acc[j][0] = fma2(h0, w2[0][0], acc[j][0]);
            acc[j][1] = fma2(h0, w2[0][1], acc[j][1]);
            acc[j][0] = fma2(h1, w2[1][0], acc[j][0]);
            acc[j][1] = fma2(h1, w2[1][1], acc[j][1]);
            acc[j][0] = fma2(h2, w2[2][0], acc[j][0]);
            acc[j][1] = fma2(h2, w2[2][1], acc[j][1]);
            acc[j][0] = fma2(h3, w2[3][0], acc[j][0]);
            acc[j][1] = fma2(h3, w2[3][1], acc[j][1]);
        }
    }

#pragma unroll
    for (int j = 0; j < 8; ++j) {
        int gn = base + n0 + j;
        if (gn < NN) {
            float2 lo = *(float2*)&acc[j][0];
            float2 hi = *(float2*)&acc[j][1];
            *(float4*)&d_z[gn * CC + lane * 4] = make_float4(lo.x, lo.y, hi.x, hi.y);
        }
    }
}

// ---------------- per-dst-node softmax aggregation + epilogue ---------------
// One warp per node; lane owns channels [4*lane, 4*lane+4).
// No max-shift needed: |e| <= ~35 so exp(e) is fp32-safe; sum(exp*zs)/sum(exp)
// equals the reference's max-shifted softmax exactly in real arithmetic.
__device__ __forceinline__ float elu1(float v) {
    return v > 0.f ? v : expm1f(v);
}

__device__ __forceinline__ void edge_accum(const float4 za, const float4 zd,
                                           float& dx, float& dy, float& dz, float& dw,
                                           float& nx, float& ny, float& nz, float& nw) {
    float ex;
    ex = __expf(za.x * zd.x); dx += ex; nx += ex * za.x;
    ex = __expf(za.y * zd.y); dy += ex; ny += ex * za.y;
    ex = __expf(za.z * zd.z); dz += ex; nz += ex * za.z;
    ex = __expf(za.w * zd.w); dw += ex; nw += ex * za.w;
}

__global__ void __launch_bounds__(256) k_agg(const float* __restrict__ hin,
                                             const float* __restrict__ snorm,
                                             float* __restrict__ out) {
    const int gwarp = (blockIdx.x * blockDim.x + threadIdx.x) >> 5;
    const int lane  = threadIdx.x & 31;
    if (gwarp >= NN) return;
    const int node = gwarp;

    const float4 zd = *(const float4*)&d_z[node * CC + lane * 4];
    float dx = 0.f, dy = 0.f, dz = 0.f, dw = 0.f;
    float nx = 0.f, ny = 0.f, nz = 0.f, nw = 0.f;

    const int p0 = d_off[node];
    const int p1 = d_off[node + 1];

    int p = p0;
    for (; p + 3 < p1; p += 4) {
        int s0 = __ldg(&d_csr_src[p]);
        int s1 = __ldg(&d_csr_src[p + 1]);
        int s2 = __ldg(&d_csr_src[p + 2]);
        int s3 = __ldg(&d_csr_src[p + 3]);
        float4 z0 = *(const float4*)&d_z[s0 * CC + lane * 4];
        float4 z1 = *(const float4*)&d_z[s1 * CC + lane * 4];
        float4 z2 = *(const float4*)&d_z[s2 * CC + lane * 4];
        float4 z3 = *(const float4*)&d_z[s3 * CC + lane * 4];
        edge_accum(z0, zd, dx, dy, dz, dw, nx, ny, nz, nw);
        edge_accum(z1, zd, dx, dy, dz, dw, nx, ny, nz, nw);
        edge_accum(z2, zd, dx, dy, dz, dw, nx, ny, nz, nw);
        edge_accum(z3, zd, dx, dy, dz, dw, nx, ny, nz, nw);
    }
    for (; p < p1; ++p) {
        int s0 = __ldg(&d_csr_src[p]);
        float4 z0 = *(const float4*)&d_z[s0 * CC + lane * 4];
        edge_accum(z0, zd, dx, dy, dz, dw, nx, ny, nz, nw);
    }

    const float sn = __ldg(&snorm[node]);
    float4 hv = *(const float4*)&hin[node * CC + lane * 4];

    float4 o;
    o.x = hv.x + elu1((dx > 0.f ? nx / dx : 0.f) * sn);
    o.y = hv.y + elu1((dy > 0.f ? ny / dy : 0.f) * sn);
    o.z = hv.z + elu1((dz > 0.f ? nz / dz : 0.f) * sn);
    o.w = hv.w + elu1((dw > 0.f ? nw / dw : 0.f) * sn);

    *(float4*)&out[node * CC + lane * 4] = o;
}

// ---------------- launch ----------------------------------------------------
extern "C" void kernel_launch(void* const* d_in, const int* in_sizes, int n_in,
                              void* d_out, int out_size) {
    const float* hin   = (const float*)d_in[0];   // [N,128]
    const float* snorm = (const float*)d_in[1];   // [N,1]
    const float* Wfc   = (const float*)d_in[2];   // [8,128,16]
    const int*   src   = (const int*)d_in[3];     // [E]
    const int*   dst   = (const int*)d_in[4];     // [E]
    float* out = (float*)d_out;                   // [N,128]

    const int gemm_smem = (KK * CC + GBM * KK) * sizeof(float);   // 96 KB
    static int smem_set = 0;
    if (!smem_set) {
        cudaFuncSetAttribute(k_gemm, cudaFuncAttributeMaxDynamicSharedMemorySize,
                             gemm_smem);
        smem_set = 1;
    }

    k_zero_cnt<<<(NN + 255) / 256, 256>>>();
    k_hist<<<(EE + 255) / 256, 256>>>(dst);
    k_scan1<<<NBLK, SB>>>();
    k_scan2<<<1, 128>>>();
    k_scan3<<<NBLK, SB>>>();
    k_scatter<<<(EE + 255) / 256, 256>>>(src, dst);
    k_gemm<<<(NN + GBM - 1) / GBM, 256, gemm_smem>>>(hin, Wfc);
    k_agg<<<(NN * 32 + 255) / 256, 256>>>(hin, snorm, out);
}

// round 5
// speedup vs baseline: 1.6366x; 1.0739x over previous
#include <cuda_runtime.h>
#include <cuda_bf16.h>
#include <cstdint>

// Problem constants (fixed shapes in the reference):
//   N=50000 nodes, E=800000 edges, IN_DIM=128, H=8, D=16 -> C = H*D = 128
#define NN 50000
#define EE 800000
#define CC 128
#define KK 128

typedef unsigned long long ull;

// ---------------- device scratch --------------------------------------------
__device__ float d_z[NN * CC];          // per-node projected features [N,128]
__device__ int   d_cnt[NN];             // in-degree histogram, then scatter cursor
__device__ int   d_off[NN + 1];         // CSR row offsets by dst
__device__ int   d_csr_src[EE];         // src node ids grouped by dst

#define SB   512
#define NBLK ((NN + SB - 1) / SB)       // 98
__device__ int d_btot[NBLK];
__device__ int d_boff[NBLK];

// ---------------- CSR construction ------------------------------------------
__global__ void k_zero_cnt() {
    int i = blockIdx.x * blockDim.x + threadIdx.x;
    if (i < NN) d_cnt[i] = 0;
}

// 4 edges per thread via one int4 load (E = 800000 is divisible by 4).
__global__ void k_hist(const int4* __restrict__ dst4) {
    int t = blockIdx.x * blockDim.x + threadIdx.x;
    if (t < EE / 4) {
        int4 d = __ldg(&dst4[t]);
        atomicAdd(&d_cnt[d.x], 1);
        atomicAdd(&d_cnt[d.y], 1);
        atomicAdd(&d_cnt[d.z], 1);
        atomicAdd(&d_cnt[d.w], 1);
    }
}

// Hierarchical scan: per-block scan -> block-total scan -> offset add.
__global__ void __launch_bounds__(SB) k_scan1() {
    __shared__ int s[SB];
    const int b = blockIdx.x, t = threadIdx.x, i = b * SB + t;
    int v = (i < NN) ? d_cnt[i] : 0;
    s[t] = v;
    __syncthreads();
    for (int o = 1; o < SB; o <<= 1) {
        int x = (t >= o) ? s[t - o] : 0;
        __syncthreads();
        s[t] += x;
        __syncthreads();
    }
    if (i < NN) d_off[i] = s[t] - v;          // exclusive within block
    if (t == SB - 1) d_btot[b] = s[t];
}

__global__ void __launch_bounds__(128) k_scan2() {
    __shared__ int s[128];
    const int t = threadIdx.x;
    int v = (t < NBLK) ? d_btot[t] : 0;
    s[t] = v;
    __syncthreads();
    for (int o = 1; o < 128; o <<= 1) {
        int x = (t >= o) ? s[t - o] : 0;
        __syncthreads();
        s[t] += x;
        __syncthreads();
    }
    if (t < NBLK) d_boff[t] = s[t] - v;       // exclusive over blocks
}

__global__ void __launch_bounds__(SB) k_scan3() {
    const int b = blockIdx.x, t = threadIdx.x, i = b * SB + t;
    if (i < NN) {
        int o = d_off[i] + d_boff[b];
        d_off[i] = o;
        d_cnt[i] = o;                          // becomes scatter cursor
    }
    if (b == 0 && t == 0) d_off[NN] = EE;
}

__global__ void k_scatter(const int* __restrict__ src, const int* __restrict__ dst) {
    int e = blockIdx.x * blockDim.x + threadIdx.x;
    if (e < EE) {
        int pos = atomicAdd(&d_cnt[dst[e]], 1);
        d_csr_src[pos] = src[e];
    }
}

// ---------------- GEMM via packed fma.rn.f32x2 ------------------------------
// z[n, h*16+d] = sum_k h[n,k] * Wcat[k, h*16+d]  (single 50000x128x128 GEMM;
// Wcat[k][h*16+d] = Wfc[h*2048 + k*16 + d]).
// Block: 256 threads, BM=64 nodes, full K=128 resident.
#define GBM 64

__device__ __forceinline__ ull fma2(ull a, ull b, ull c) {
    ull d;
    asm("fma.rn.f32x2 %0, %1, %2, %3;" : "=l"(d) : "l"(a), "l"(b), "l"(c));
    return d;
}
__device__ __forceinline__ ull pack2(float x) {
    ull d;
    asm("mov.b64 %0, {%1, %1};" : "=l"(d) : "f"(x));
    return d;
}

__global__ void __launch_bounds__(256) k_gemm(const float* __restrict__ hin,
                                              const float* __restrict__ Wfc) {
    extern __shared__ float smem[];
    float* sW = smem;                  // [128][128]  sW[k*128 + c]
    float* sH = smem + KK * CC;        // [64][128]   sH[node*128 + k]

    const int tid  = threadIdx.x;
    const int lane = tid & 31;
    const int warp = tid >> 5;
    const int base = blockIdx.x * GBM;
    const int n0   = warp * 8;

    // Load W (transposed to [k][c]): dst float4 index g -> k=g>>5, h=(g>>2)&7, dq=g&3
    {
        const float4* W4 = (const float4*)Wfc;
        float4* sW4 = (float4*)sW;
        for (int g = tid; g < KK * CC / 4; g += 256) {
            int k  = g >> 5;
            int hh = (g >> 2) & 7;
            int dq = g & 3;
            sW4[g] = W4[hh * 512 + k * 4 + dq];
        }
    }
    // Load H tile [64][128]
    {
        const float4* H4 = (const float4*)hin;
        float4* sH4 = (float4*)sH;
        for (int g = tid; g < GBM * KK / 4; g += 256) {
            int row = g >> 5;
            int kq  = g & 31;
            int gn  = base + row;
            sH4[g] = (gn < NN) ? H4[gn * 32 + kq]
                               : make_float4(0.f, 0.f, 0.f, 0.f);
        }
    }
    __syncthreads();

    ull acc[8][2];
#pragma unroll
    for (int j = 0; j < 8; ++j) { acc[j][0] = 0ull; acc[j][1] = 0ull; }

    for (int k = 0; k < KK; k += 4) {
        ull w2[4][2];
#pragma unroll
        for (int kk = 0; kk < 4; ++kk) {
            ulonglong2 wv = *(const ulonglong2*)&sW[(k + kk) * CC + lane * 4];
            w2[kk][0] = wv.x;
            w2[kk][1] = wv.y;
        }
#pragma unroll
        for (int j = 0; j < 8; ++j) {
            const float4 hj = *(const float4*)&sH[(n0 + j) * KK + k];
            ull h0 = pack2(hj.x), h1 = pack2(hj.y), h2 = pack2(hj.z), h3 = pack2(hj.w);
            acc[j][0] = fma2(h0, w2[0][0], acc[j][0]);
            acc[j][1] = fma2(h0, w2[0][1], acc[j][1]);
            acc[j][0] = fma2(h1, w2[1][0], acc[j][0]);
            acc[j][1] = fma2(h1, w2[1][1], acc[j][1]);
            acc[j][0] = fma2(h2, w2[2][0], acc[j][0]);
            acc[j][1] = fma2(h2, w2[2][1], acc[j][1]);
            acc[j][0] = fma2(h3, w2[3][0], acc[j][0]);
            acc[j][1] = fma2(h3, w2[3][1], acc[j][1]);
        }
    }

#pragma unroll
    for (int j = 0; j < 8; ++j) {
        int gn = base + n0 + j;
        if (gn < NN) {
            float2 lo = *(float2*)&acc[j][0];
            float2 hi = *(float2*)&acc[j][1];
            *(float4*)&d_z[gn * CC + lane * 4] = make_float4(lo.x, lo.y, hi.x, hi.y);
        }
    }
}

// ---------------- per-dst-node softmax aggregation + epilogue ---------------
// One warp per node; lane owns channels [4*lane, 4*lane+4).
// No max-shift needed: |e| <= ~35 so exp(e) is fp32-safe; sum(exp*zs)/sum(exp)
// equals the reference's max-shifted softmax exactly in real arithmetic.
__device__ __forceinline__ float elu1(float v) {
    return v > 0.f ? v : expm1f(v);
}

__device__ __forceinline__ void edge_accum(const float4 za, const float4 zd,
                                           float& dx, float& dy, float& dz, float& dw,
                                           float& nx, float& ny, float& nz, float& nw) {
    float ex;
    ex = __expf(za.x * zd.x); dx += ex; nx += ex * za.x;
    ex = __expf(za.y * zd.y); dy += ex; ny += ex * za.y;
    ex = __expf(za.z * zd.z); dz += ex; nz += ex * za.z;
    ex = __expf(za.w * zd.w); dw += ex; nw += ex * za.w;
}

__global__ void __launch_bounds__(256) k_agg(const float* __restrict__ hin,
                                             const float* __restrict__ snorm,
                                             float* __restrict__ out) {
    const int gwarp = (blockIdx.x * blockDim.x + threadIdx.x) >> 5;
    const int lane  = threadIdx.x & 31;
    if (gwarp >= NN) return;
    const int node = gwarp;

    const float4 zd = *(const float4*)&d_z[node * CC + lane * 4];
    float dx = 0.f, dy = 0.f, dz = 0.f, dw = 0.f;
    float nx = 0.f, ny = 0.f, nz = 0.f, nw = 0.f;

    const int p0 = d_off[node];
    const int p1 = d_off[node + 1];

    int p = p0;
    for (; p + 3 < p1; p += 4) {
        int s0 = __ldg(&d_csr_src[p]);
        int s1 = __ldg(&d_csr_src[p + 1]);
        int s2 = __ldg(&d_csr_src[p + 2]);
        int s3 = __ldg(&d_csr_src[p + 3]);
        float4 z0 = *(const float4*)&d_z[s0 * CC + lane * 4];
        float4 z1 = *(const float4*)&d_z[s1 * CC + lane * 4];
        float4 z2 = *(const float4*)&d_z[s2 * CC + lane * 4];
        float4 z3 = *(const float4*)&d_z[s3 * CC + lane * 4];
        edge_accum(z0, zd, dx, dy, dz, dw, nx, ny, nz, nw);
        edge_accum(z1, zd, dx, dy, dz, dw, nx, ny, nz, nw);
        edge_accum(z2, zd, dx, dy, dz, dw, nx, ny, nz, nw);
        edge_accum(z3, zd, dx, dy, dz, dw, nx, ny, nz, nw);
    }
    for (; p < p1; ++p) {
        int s0 = __ldg(&d_csr_src[p]);
        float4 z0 = *(const float4*)&d_z[s0 * CC + lane * 4];
        edge_accum(z0, zd, dx, dy, dz, dw, nx, ny, nz, nw);
    }

    const float sn = __ldg(&snorm[node]);
    float4 hv = *(const float4*)&hin[node * CC + lane * 4];

    float4 o;
    o.x = hv.x + elu1((dx > 0.f ? nx / dx : 0.f) * sn);
    o.y = hv.y + elu1((dy > 0.f ? ny / dy : 0.f) * sn);
    o.z = hv.z + elu1((dz > 0.f ? nz / dz : 0.f) * sn);
    o.w = hv.w + elu1((dw > 0.f ? nw / dw : 0.f) * sn);

    *(float4*)&out[node * CC + lane * 4] = o;
}

// ---------------- launch ----------------------------------------------------
// CSR chain runs on the default stream; the independent GEMM is forked onto a
// second non-blocking stream (created once, on the first uncaptured call) so
// it overlaps the atomic-bound CSR build. k_agg joins both via an event.
extern "C" void kernel_launch(void* const* d_in, const int* in_sizes, int n_in,
                              void* d_out, int out_size) {
    const float* hin   = (const float*)d_in[0];   // [N,128]
    const float* snorm = (const float*)d_in[1];   // [N,1]
    const float* Wfc   = (const float*)d_in[2];   // [8,128,16]
    const int*   src   = (const int*)d_in[3];     // [E]
    const int*   dst   = (const int*)d_in[4];     // [E]
    float* out = (float*)d_out;                   // [N,128]

    const int gemm_smem = (KK * CC + GBM * KK) * sizeof(float);   // 96 KB

    static int init_done = 0;
    static cudaStream_t s2 = 0;
    static cudaEvent_t evFork = 0, evJoin = 0;
    if (!init_done) {
        cudaFuncSetAttribute(k_gemm, cudaFuncAttributeMaxDynamicSharedMemorySize,
                             gemm_smem);
        if (cudaStreamCreateWithFlags(&s2, cudaStreamNonBlocking) != cudaSuccess)
            s2 = 0;
        if (s2) {
            if (cudaEventCreateWithFlags(&evFork, cudaEventDisableTiming) != cudaSuccess ||
                cudaEventCreateWithFlags(&evJoin, cudaEventDisableTiming) != cudaSuccess) {
                s2 = 0;   // fall back to serial, deterministically, forever
            }
        }
        init_done = 1;
    }

    if (s2) {
        // Fork GEMM onto s2 (depends only on hin/Wfc).
        cudaEventRecord(evFork, 0);
        cudaStreamWaitEvent(s2, evFork, 0);
        k_gemm<<<(NN + GBM - 1) / GBM, 256, gemm_smem, s2>>>(hin, Wfc);
        cudaEventRecord(evJoin, s2);
    }

    // CSR build chain on the default stream.
    k_zero_cnt<<<(NN + 255) / 256, 256>>>();
    k_hist<<<(EE / 4 + 255) / 256, 256>>>((const int4*)dst);
    k_scan1<<<NBLK, SB>>>();
    k_scan2<<<1, 128>>>();
    k_scan3<<<NBLK, SB>>>();
    k_scatter<<<(EE + 255) / 256, 256>>>(src, dst);

    if (s2) {
        cudaStreamWaitEvent(0, evJoin, 0);    // join: agg needs d_z + CSR
    } else {
        k_gemm<<<(NN + GBM - 1) / GBM, 256, gemm_smem>>>(hin, Wfc);
    }

    k_agg<<<(NN * 32 + 255) / 256, 256>>>(hin, snorm, out);
}